// round 1
// baseline (speedup 1.0000x reference)
#include <cuda_runtime.h>
#include <math.h>

// Problem constants
#define BB 4
#define MM 500   // rows (pred2)
#define NN 500   // cols (pred1)
#define CC 91
#define NPAD 512

// Scratch (device globals; no allocation allowed)
__device__ float g_s1[BB * NN * CC];   // sigmoid(pred1_logits)
__device__ float g_s2[BB * MM * CC];   // sigmoid(pred2_logits)
__device__ float g_cost[BB * MM * NN]; // cost matrix (fp32; cast to fp64 in LSA)
__device__ int   g_map[BB * MM];       // row -> col assignment

// ---------------------------------------------------------------------------
// 1) sigmoids
// ---------------------------------------------------------------------------
__global__ void sigmoid_kernel(const float* __restrict__ l1,
                               const float* __restrict__ l2) {
    int idx = blockIdx.x * blockDim.x + threadIdx.x;
    const int n1 = BB * NN * CC;
    const int n2 = BB * MM * CC;
    if (idx < n1) {
        float x = l1[idx];
        g_s1[idx] = 1.0f / (1.0f + expf(-x));
    } else if (idx < n1 + n2) {
        float x = l2[idx - n1];
        g_s2[idx - n1] = 1.0f / (1.0f + expf(-x));
    }
}

// ---------------------------------------------------------------------------
// 2) cost matrix: cost[b][i][j] = 0.5*||c2_i - c1_j||2 + 0.5*max_c|s2-s1|
//    tiled 32x32 (i x j) per block
// ---------------------------------------------------------------------------
__global__ __launch_bounds__(1024) void cost_kernel(
        const float* __restrict__ p1_boxes,
        const float* __restrict__ p2_boxes) {
    const int b = blockIdx.z;
    const int i0 = blockIdx.y * 32;
    const int j0 = blockIdx.x * 32;

    __shared__ float s2t[32][CC];
    __shared__ float s1t[32][CC];
    __shared__ float b2x[32], b2y[32], b1x[32], b1y[32];

    const int tx = threadIdx.x;  // j within tile
    const int ty = threadIdx.y;  // i within tile
    const int tid = ty * 32 + tx;

    for (int idx = tid; idx < 32 * CC; idx += 1024) {
        int r = idx / CC, c = idx % CC;
        int gi = i0 + r;
        int gj = j0 + r;
        s2t[r][c] = (gi < MM) ? g_s2[(b * MM + gi) * CC + c] : 0.0f;
        s1t[r][c] = (gj < NN) ? g_s1[(b * NN + gj) * CC + c] : 0.0f;
    }
    if (ty == 0) {
        int gi = i0 + tx;
        if (gi < MM) {
            b2x[tx] = p2_boxes[(b * MM + gi) * 4 + 0];
            b2y[tx] = p2_boxes[(b * MM + gi) * 4 + 1];
        }
    } else if (ty == 1) {
        int gj = j0 + tx;
        if (gj < NN) {
            b1x[tx] = p1_boxes[(b * NN + gj) * 4 + 0];
            b1y[tx] = p1_boxes[(b * NN + gj) * 4 + 1];
        }
    }
    __syncthreads();

    const int i = i0 + ty;
    const int j = j0 + tx;
    if (i < MM && j < NN) {
        float mx = 0.0f;
        #pragma unroll
        for (int c = 0; c < CC; c++) {
            mx = fmaxf(mx, fabsf(s2t[ty][c] - s1t[tx][c]));
        }
        float dx = __fadd_rn(b2x[ty], -b1x[tx]);
        float dy = __fadd_rn(b2y[ty], -b1y[tx]);
        float cd = __fsqrt_rn(__fadd_rn(__fmul_rn(dx, dx), __fmul_rn(dy, dy)));
        g_cost[(b * MM + i) * NN + j] =
            __fadd_rn(__fmul_rn(0.5f, cd), __fmul_rn(0.5f, mx));
    }
}

// ---------------------------------------------------------------------------
// 3) exact LSA (shortest augmenting path, scipy rectangular_lsap port)
//    one warp per batch; fp64 to match numpy exactly; first-index tie-break
// ---------------------------------------------------------------------------
__global__ __launch_bounds__(32) void lsa_kernel() {
    const int n = NN;              // square: 500
    const int b = blockIdx.x;
    const int lane = threadIdx.x;
    const float* cost = g_cost + b * n * n;
    const double DINF = __longlong_as_double(0x7ff0000000000000LL);

    __shared__ double sh_u[MM];
    __shared__ double sh_short[NPAD];
    __shared__ int sh_path[NPAD];
    __shared__ int sh_col4row[MM];
    __shared__ int sh_row4col[NPAD];
    __shared__ int sh_SR[MM];

    // per-lane column ownership: j = k*32 + lane, k in [0,16)
    double v[16];
    #pragma unroll
    for (int k = 0; k < 16; k++) v[k] = 0.0;

    for (int t = lane; t < n; t += 32) {
        sh_u[t] = 0.0;
        sh_col4row[t] = -1;
        sh_row4col[t] = -1;
    }
    __syncwarp();

    for (int cur = 0; cur < n; cur++) {
        double minv = 0.0;
        int i = cur;
        unsigned rem = 0xFFFFu;
        #pragma unroll
        for (int k = 0; k < 16; k++) {
            int j = k * 32 + lane;
            if (j < n) { sh_short[j] = DINF; sh_path[j] = -1; }
        }
        int nSR = 0;
        int sink = -1;
        __syncwarp();

        while (sink < 0) {
            if (lane == 0) sh_SR[nSR] = i;
            nSR++;
            double ui = sh_u[i];
            const float* crow = cost + i * n;
            // relax owned remaining columns
            #pragma unroll
            for (int k = 0; k < 16; k++) {
                int j = k * 32 + lane;
                if (((rem >> k) & 1u) && j < n) {
                    double r = ((minv + (double)__ldg(crow + j)) - ui) - v[k];
                    if (r < sh_short[j]) {
                        sh_short[j] = r;
                        sh_path[j] = i;
                    }
                }
            }
            // local argmin over remaining owned columns (ascending j)
            double bv = DINF;
            int bj = 0x7fffffff;
            #pragma unroll
            for (int k = 0; k < 16; k++) {
                int j = k * 32 + lane;
                if (((rem >> k) & 1u) && j < n) {
                    double s = sh_short[j];
                    if (s < bv) { bv = s; bj = j; }
                }
            }
            // warp lexicographic reduction (min value, then min index)
            #pragma unroll
            for (int off = 16; off > 0; off >>= 1) {
                double ov = __shfl_down_sync(0xffffffffu, bv, off);
                int    oj = __shfl_down_sync(0xffffffffu, bj, off);
                if (ov < bv || (ov == bv && oj < bj)) { bv = ov; bj = oj; }
            }
            bv = __shfl_sync(0xffffffffu, bv, 0);
            bj = __shfl_sync(0xffffffffu, bj, 0);
            minv = bv;
            int jm = bj;
            if (lane == (jm & 31)) rem &= ~(1u << (jm >> 5));
            int r4c = sh_row4col[jm];
            if (r4c == -1) sink = jm;
            else i = r4c;
        }
        __syncwarp();   // make shortest/path/SR visible warp-wide

        if (lane == 0) sh_u[cur] += minv;
        // u[SR[1:]] += minv - shortest[col4row[SR]]
        for (int s = 1 + lane; s < nSR; s += 32) {
            int row = sh_SR[s];
            sh_u[row] += minv - sh_short[sh_col4row[row]];
        }
        // v[scanned] -= minv - shortest[scanned]  (owned columns)
        #pragma unroll
        for (int k = 0; k < 16; k++) {
            int j = k * 32 + lane;
            if (j < n && !((rem >> k) & 1u)) {
                v[k] -= (minv - sh_short[j]);
            }
        }
        __syncwarp();
        // augment along alternating path (sequential, lane 0)
        if (lane == 0) {
            int j = sink;
            while (true) {
                int ii = sh_path[j];
                sh_row4col[j] = ii;
                int tcol = sh_col4row[ii];
                sh_col4row[ii] = j;
                j = tcol;
                if (ii == cur) break;
            }
        }
        __syncwarp();
    }

    for (int t = lane; t < n; t += 32) g_map[b * n + t] = sh_col4row[t];
}

// ---------------------------------------------------------------------------
// 4) extrapolation + output write
//    out layout: boxes3 (B*M*4 floats) then logits3 (B*M*C floats)
// ---------------------------------------------------------------------------
__global__ void extrap_kernel(const float* __restrict__ p1_boxes,
                              const float* __restrict__ p1_logits,
                              const float* __restrict__ p2_boxes,
                              const float* __restrict__ p2_logits,
                              const float* __restrict__ toff,
                              float* __restrict__ out) {
    int idx = blockIdx.x * blockDim.x + threadIdx.x;
    const int boxTotal = BB * MM * 4;
    const int logTotal = BB * MM * CC;
    if (idx < boxTotal) {
        int d = idx & 3;
        int bi = idx >> 2;
        int b = bi / MM;
        float first  = toff[b * 3 + 1] - toff[b * 3 + 0];
        float second = toff[b * 3 + 2] - toff[b * 3 + 1];
        float factor = second / first;
        int mcol = g_map[bi];
        float b2 = p2_boxes[idx];
        float c1 = p1_boxes[(b * NN + mcol) * 4 + d];
        float val = b2 + (b2 - c1) * factor;
        if (d >= 2) val = fmaxf(val, 0.0f);
        out[idx] = val;
    } else if (idx < boxTotal + logTotal) {
        int t = idx - boxTotal;
        int c = t % CC;
        int bi = t / CC;
        int b = bi / MM;
        int mcol = g_map[bi];
        float l2 = p2_logits[t];
        float l1 = p1_logits[(b * NN + mcol) * CC + c];
        out[idx] = 0.5f * (l2 + l1);
    }
}

// ---------------------------------------------------------------------------
extern "C" void kernel_launch(void* const* d_in, const int* in_sizes, int n_in,
                              void* d_out, int out_size) {
    const float* p1_boxes  = (const float*)d_in[0];
    const float* p1_logits = (const float*)d_in[1];
    const float* p2_boxes  = (const float*)d_in[2];
    const float* p2_logits = (const float*)d_in[3];
    const float* toff      = (const float*)d_in[4];
    float* out = (float*)d_out;

    // 1) sigmoids
    {
        int total = BB * NN * CC + BB * MM * CC;
        int threads = 256;
        int blocks = (total + threads - 1) / threads;
        sigmoid_kernel<<<blocks, threads>>>(p1_logits, p2_logits);
    }
    // 2) cost matrix
    {
        dim3 grid((NN + 31) / 32, (MM + 31) / 32, BB);
        dim3 block(32, 32);
        cost_kernel<<<grid, block>>>(p1_boxes, p2_boxes);
    }
    // 3) exact assignment (warp per batch)
    lsa_kernel<<<BB, 32>>>();
    // 4) extrapolation
    {
        int total = BB * MM * 4 + BB * MM * CC;
        int threads = 256;
        int blocks = (total + threads - 1) / threads;
        extrap_kernel<<<blocks, threads>>>(p1_boxes, p1_logits, p2_boxes,
                                           p2_logits, toff, out);
    }
}

// round 2
// speedup vs baseline: 2.3122x; 2.3122x over previous
#include <cuda_runtime.h>
#include <math.h>

// Problem constants
#define BB 4
#define MM 500   // rows (pred2)
#define NN 500   // cols (pred1)
#define CC 91
#define NPAD 512
#define FULLMASK 0xffffffffu
#define MARGIN 1e-4f

// Scratch (device globals; no allocation allowed)
__device__ float g_s1[BB * NN * CC];   // sigmoid(pred1_logits)
__device__ float g_s2[BB * MM * CC];   // sigmoid(pred2_logits)
__device__ __align__(16) float g_cost[BB * MM * NPAD]; // padded cost rows
__device__ int   g_map[BB * MM];       // row -> col assignment

// ---------------------------------------------------------------------------
// 1) sigmoids
// ---------------------------------------------------------------------------
__global__ void sigmoid_kernel(const float* __restrict__ l1,
                               const float* __restrict__ l2) {
    int idx = blockIdx.x * blockDim.x + threadIdx.x;
    const int n1 = BB * NN * CC;
    const int n2 = BB * MM * CC;
    if (idx < n1) {
        float x = l1[idx];
        g_s1[idx] = 1.0f / (1.0f + expf(-x));
    } else if (idx < n1 + n2) {
        float x = l2[idx - n1];
        g_s2[idx - n1] = 1.0f / (1.0f + expf(-x));
    }
}

// ---------------------------------------------------------------------------
// 2) cost matrix: cost[b][i][j] = 0.5*||c2_i - c1_j||2 + 0.5*max_c|s2-s1|
//    rows padded to NPAD with +inf-ish sentinel
// ---------------------------------------------------------------------------
__global__ __launch_bounds__(1024) void cost_kernel(
        const float* __restrict__ p1_boxes,
        const float* __restrict__ p2_boxes) {
    const int b = blockIdx.z;
    const int i0 = blockIdx.y * 32;
    const int j0 = blockIdx.x * 32;

    __shared__ float s2t[32][CC];
    __shared__ float s1t[32][CC];
    __shared__ float b2x[32], b2y[32], b1x[32], b1y[32];

    const int tx = threadIdx.x;  // j within tile
    const int ty = threadIdx.y;  // i within tile
    const int tid = ty * 32 + tx;

    for (int idx = tid; idx < 32 * CC; idx += 1024) {
        int r = idx / CC, c = idx % CC;
        int gi = i0 + r;
        int gj = j0 + r;
        s2t[r][c] = (gi < MM) ? g_s2[(b * MM + gi) * CC + c] : 0.0f;
        s1t[r][c] = (gj < NN) ? g_s1[(b * NN + gj) * CC + c] : 0.0f;
    }
    if (ty == 0) {
        int gi = i0 + tx;
        if (gi < MM) {
            b2x[tx] = p2_boxes[(b * MM + gi) * 4 + 0];
            b2y[tx] = p2_boxes[(b * MM + gi) * 4 + 1];
        }
    } else if (ty == 1) {
        int gj = j0 + tx;
        if (gj < NN) {
            b1x[tx] = p1_boxes[(b * NN + gj) * 4 + 0];
            b1y[tx] = p1_boxes[(b * NN + gj) * 4 + 1];
        }
    }
    __syncthreads();

    const int i = i0 + ty;
    const int j = j0 + tx;
    if (i < MM) {
        if (j < NN) {
            float mx = 0.0f;
            #pragma unroll
            for (int c = 0; c < CC; c++) {
                mx = fmaxf(mx, fabsf(s2t[ty][c] - s1t[tx][c]));
            }
            float dx = __fadd_rn(b2x[ty], -b1x[tx]);
            float dy = __fadd_rn(b2y[ty], -b1y[tx]);
            float cd = __fsqrt_rn(__fadd_rn(__fmul_rn(dx, dx), __fmul_rn(dy, dy)));
            g_cost[(b * MM + i) * NPAD + j] =
                __fadd_rn(__fmul_rn(0.5f, cd), __fmul_rn(0.5f, mx));
        } else {
            g_cost[(b * MM + i) * NPAD + j] = 1e30f;  // padding
        }
    }
}

// ---------------------------------------------------------------------------
// 3) exact LSA (shortest augmenting path, scipy rectangular_lsap semantics)
//    one warp per batch. fp32 margin-pruned sweep, fp64 exact updates only
//    where needed. Lane L owns contiguous columns [L*16, L*16+16).
// ---------------------------------------------------------------------------
__global__ __launch_bounds__(32) void lsa_kernel() {
    const int b = blockIdx.x;
    const int lane = threadIdx.x;
    const double DINF = __longlong_as_double(0x7ff0000000000000LL);
    const float  FINF = __int_as_float(0x7f800000);

    __shared__ double u64s[MM];
    __shared__ double v64s[NPAD];
    __shared__ double s64s[NPAD];
    __shared__ __align__(16) float v32s[NPAD];
    __shared__ __align__(16) float s32s[NPAD];
    __shared__ int paths[NPAD];
    __shared__ int col4rows[MM];
    __shared__ int row4cols[NPAD];
    __shared__ int SRs[MM];

    // global init
    for (int t = lane; t < NPAD; t += 32) {
        v64s[t] = 0.0; v32s[t] = 0.0f; row4cols[t] = -1;
        if (t < MM) { u64s[t] = 0.0; col4rows[t] = -1; }
    }
    const int base = lane * 16;
    unsigned validMask;
    {
        int nvalid = NN - base;
        if (nvalid < 0) nvalid = 0;
        if (nvalid > 16) nvalid = 16;
        validMask = (nvalid == 16) ? 0xffffu : ((1u << nvalid) - 1u);
    }
    __syncwarp();

    const float* costB = g_cost + (size_t)b * MM * NPAD;

    for (int cur = 0; cur < MM; cur++) {
        // per-round init of this lane's columns
        #pragma unroll
        for (int kk = 0; kk < 16; kk++) {
            s64s[base + kk] = DINF;
            s32s[base + kk] = FINF;
            paths[base + kk] = -1;
        }
        unsigned rem = validMask;
        unsigned scanned = 0;
        double minv = 0.0;
        int i = cur;
        int nSR = 0;
        int sink = -1;
        __syncwarp();

        while (true) {
            if (lane == 0) SRs[nSR] = i;
            nSR++;
            double dd = minv - u64s[i];
            float dd32 = (float)dd;
            const float* crow = costB + (size_t)i * NPAD + base;

            // fp32 margin sweep over owned columns
            float4 c4[4];
            c4[0] = __ldg((const float4*)(crow + 0));
            c4[1] = __ldg((const float4*)(crow + 4));
            c4[2] = __ldg((const float4*)(crow + 8));
            c4[3] = __ldg((const float4*)(crow + 12));
            float bm = FINF;
            unsigned candMask = 0;
            #pragma unroll
            for (int q = 0; q < 4; q++) {
                float4 vv = *(const float4*)(v32s + base + q * 4);
                float4 sv = *(const float4*)(s32s + base + q * 4);
                float cA[4] = {c4[q].x, c4[q].y, c4[q].z, c4[q].w};
                float vA[4] = {vv.x, vv.y, vv.z, vv.w};
                float sA[4] = {sv.x, sv.y, sv.z, sv.w};
                #pragma unroll
                for (int e = 0; e < 4; e++) {
                    int kk = q * 4 + e;
                    float r = (cA[e] - vA[e]) + dd32;
                    bool remb = (rem >> kk) & 1u;
                    bool cand = remb && (r < sA[e] + MARGIN);
                    if (cand) candMask |= (1u << kk);
                    float s_eff = cand ? fminf(sA[e], r) : sA[e];
                    bm = fminf(bm, s_eff);
                }
            }
            // exact fp64 updates only for candidates
            while (candMask) {
                int kk = __ffs(candMask) - 1;
                candMask &= candMask - 1;
                int j = base + kk;
                double c64 = (double)__ldg(crow + kk);
                double r = (c64 - v64s[j]) + dd;
                if (r < s64s[j]) {
                    s64s[j] = r;
                    float rf = (float)r;
                    s32s[j] = rf;
                    paths[j] = i;
                    bm = fminf(bm, rf);
                }
            }
            // approximate global min via REDUX on ordered fp32 bits
            unsigned ub = __float_as_uint(bm);
            unsigned key = (ub & 0x80000000u) ? ~ub : (ub | 0x80000000u);
            unsigned mk = __reduce_min_sync(FULLMASK, key);
            float m32 = (mk & 0x80000000u) ? __uint_as_float(mk & 0x7fffffffu)
                                           : __uint_as_float(~mk);
            float thr = m32 + MARGIN;
            // exact resolution among candidates within margin
            double bestV = DINF;
            int bestJ = 0x7fffffff;
            if (bm <= thr) {
                unsigned mm2 = rem;
                while (mm2) {
                    int kk = __ffs(mm2) - 1;
                    mm2 &= mm2 - 1;
                    int j = base + kk;
                    if (s32s[j] <= thr) {
                        double sv = s64s[j];
                        if (sv < bestV) { bestV = sv; bestJ = j; }  // ascending j => first-index tie-break
                    }
                }
            }
            unsigned bal = __ballot_sync(FULLMASK, bestJ != 0x7fffffff);
            int jm;
            if (__popc(bal) == 1) {
                int src = __ffs(bal) - 1;
                minv = __shfl_sync(FULLMASK, bestV, src);
                jm   = __shfl_sync(FULLMASK, bestJ, src);
            } else {
                #pragma unroll
                for (int off = 16; off > 0; off >>= 1) {
                    double ov = __shfl_down_sync(FULLMASK, bestV, off);
                    int    oj = __shfl_down_sync(FULLMASK, bestJ, off);
                    if (ov < bestV || (ov == bestV && oj < bestJ)) { bestV = ov; bestJ = oj; }
                }
                minv = __shfl_sync(FULLMASK, bestV, 0);
                jm   = __shfl_sync(FULLMASK, bestJ, 0);
            }
            // remove column jm, fetch its row
            int owner = jm >> 4;
            int r4c = 0;
            if (lane == owner) {
                rem &= ~(1u << (jm & 15));
                scanned |= (1u << (jm & 15));
                s32s[jm] = FINF;
                r4c = row4cols[jm];
            }
            r4c = __shfl_sync(FULLMASK, r4c, owner);
            if (r4c < 0) { sink = jm; break; }
            i = r4c;
        }
        __syncwarp();

        // dual updates (exact fp64, scipy order)
        for (int s = lane; s < nSR; s += 32) {
            int row = SRs[s];
            if (s == 0) u64s[row] += minv;
            else        u64s[row] += minv - s64s[col4rows[row]];
        }
        {
            unsigned sm2 = scanned;
            while (sm2) {
                int kk = __ffs(sm2) - 1;
                sm2 &= sm2 - 1;
                int j = base + kk;
                double nv = v64s[j] - (minv - s64s[j]);
                v64s[j] = nv;
                v32s[j] = (float)nv;
            }
        }
        __syncwarp();
        // augment along alternating path
        if (lane == 0) {
            int j = sink;
            while (true) {
                int ii = paths[j];
                row4cols[j] = ii;
                int t = col4rows[ii];
                col4rows[ii] = j;
                j = t;
                if (ii == cur) break;
            }
        }
        __syncwarp();
    }

    for (int t = lane; t < MM; t += 32) g_map[b * MM + t] = col4rows[t];
}

// ---------------------------------------------------------------------------
// 4) extrapolation + output write
//    out layout: boxes3 (B*M*4 floats) then logits3 (B*M*C floats)
// ---------------------------------------------------------------------------
__global__ void extrap_kernel(const float* __restrict__ p1_boxes,
                              const float* __restrict__ p1_logits,
                              const float* __restrict__ p2_boxes,
                              const float* __restrict__ p2_logits,
                              const float* __restrict__ toff,
                              float* __restrict__ out) {
    int idx = blockIdx.x * blockDim.x + threadIdx.x;
    const int boxTotal = BB * MM * 4;
    const int logTotal = BB * MM * CC;
    if (idx < boxTotal) {
        int d = idx & 3;
        int bi = idx >> 2;
        int b = bi / MM;
        float first  = toff[b * 3 + 1] - toff[b * 3 + 0];
        float second = toff[b * 3 + 2] - toff[b * 3 + 1];
        float factor = second / first;
        int mcol = g_map[bi];
        float b2 = p2_boxes[idx];
        float c1 = p1_boxes[(b * NN + mcol) * 4 + d];
        float val = b2 + (b2 - c1) * factor;
        if (d >= 2) val = fmaxf(val, 0.0f);
        out[idx] = val;
    } else if (idx < boxTotal + logTotal) {
        int t = idx - boxTotal;
        int c = t % CC;
        int bi = t / CC;
        int b = bi / MM;
        int mcol = g_map[bi];
        float l2 = p2_logits[t];
        float l1 = p1_logits[(b * NN + mcol) * CC + c];
        out[idx] = 0.5f * (l2 + l1);
    }
}

// ---------------------------------------------------------------------------
extern "C" void kernel_launch(void* const* d_in, const int* in_sizes, int n_in,
                              void* d_out, int out_size) {
    const float* p1_boxes  = (const float*)d_in[0];
    const float* p1_logits = (const float*)d_in[1];
    const float* p2_boxes  = (const float*)d_in[2];
    const float* p2_logits = (const float*)d_in[3];
    const float* toff      = (const float*)d_in[4];
    float* out = (float*)d_out;

    // 1) sigmoids
    {
        int total = BB * NN * CC + BB * MM * CC;
        int threads = 256;
        int blocks = (total + threads - 1) / threads;
        sigmoid_kernel<<<blocks, threads>>>(p1_logits, p2_logits);
    }
    // 2) cost matrix (padded rows)
    {
        dim3 grid(NPAD / 32, (MM + 31) / 32, BB);
        dim3 block(32, 32);
        cost_kernel<<<grid, block>>>(p1_boxes, p2_boxes);
    }
    // 3) exact assignment (warp per batch)
    lsa_kernel<<<BB, 32>>>();
    // 4) extrapolation
    {
        int total = BB * MM * 4 + BB * MM * CC;
        int threads = 256;
        int blocks = (total + threads - 1) / threads;
        extrap_kernel<<<blocks, threads>>>(p1_boxes, p1_logits, p2_boxes,
                                           p2_logits, toff, out);
    }
}

// round 3
// speedup vs baseline: 3.6035x; 1.5585x over previous
#include <cuda_runtime.h>
#include <math.h>

// Problem constants
#define BB 4
#define MM 500   // rows (pred2)
#define NN 500   // cols (pred1)
#define CC 91
#define NPAD 512
#define FULLMASK 0xffffffffu
#define MARGIN 1e-4f

// Scratch (device globals; no allocation allowed)
__device__ float g_s1[BB * NN * CC];   // sigmoid(pred1_logits)
__device__ float g_s2[BB * MM * CC];   // sigmoid(pred2_logits)
__device__ __align__(16) float g_cost[BB * MM * NPAD]; // padded cost rows
__device__ int   g_map[BB * MM];       // row -> col assignment

// ---------------------------------------------------------------------------
// 1) sigmoids
// ---------------------------------------------------------------------------
__global__ void sigmoid_kernel(const float* __restrict__ l1,
                               const float* __restrict__ l2) {
    int idx = blockIdx.x * blockDim.x + threadIdx.x;
    const int n1 = BB * NN * CC;
    const int n2 = BB * MM * CC;
    if (idx < n1) {
        float x = l1[idx];
        g_s1[idx] = 1.0f / (1.0f + expf(-x));
    } else if (idx < n1 + n2) {
        float x = l2[idx - n1];
        g_s2[idx - n1] = 1.0f / (1.0f + expf(-x));
    }
}

// ---------------------------------------------------------------------------
// 2) cost matrix: cost[b][i][j] = 0.5*||c2_i - c1_j||2 + 0.5*max_c|s2-s1|
// ---------------------------------------------------------------------------
__global__ __launch_bounds__(1024) void cost_kernel(
        const float* __restrict__ p1_boxes,
        const float* __restrict__ p2_boxes) {
    const int b = blockIdx.z;
    const int i0 = blockIdx.y * 32;
    const int j0 = blockIdx.x * 32;

    __shared__ float s2t[32][CC];
    __shared__ float s1t[32][CC];
    __shared__ float b2x[32], b2y[32], b1x[32], b1y[32];

    const int tx = threadIdx.x;
    const int ty = threadIdx.y;
    const int tid = ty * 32 + tx;

    for (int idx = tid; idx < 32 * CC; idx += 1024) {
        int r = idx / CC, c = idx % CC;
        int gi = i0 + r;
        int gj = j0 + r;
        s2t[r][c] = (gi < MM) ? g_s2[(b * MM + gi) * CC + c] : 0.0f;
        s1t[r][c] = (gj < NN) ? g_s1[(b * NN + gj) * CC + c] : 0.0f;
    }
    if (ty == 0) {
        int gi = i0 + tx;
        if (gi < MM) {
            b2x[tx] = p2_boxes[(b * MM + gi) * 4 + 0];
            b2y[tx] = p2_boxes[(b * MM + gi) * 4 + 1];
        }
    } else if (ty == 1) {
        int gj = j0 + tx;
        if (gj < NN) {
            b1x[tx] = p1_boxes[(b * NN + gj) * 4 + 0];
            b1y[tx] = p1_boxes[(b * NN + gj) * 4 + 1];
        }
    }
    __syncthreads();

    const int i = i0 + ty;
    const int j = j0 + tx;
    if (i < MM) {
        if (j < NN) {
            float mx = 0.0f;
            #pragma unroll
            for (int c = 0; c < CC; c++) {
                mx = fmaxf(mx, fabsf(s2t[ty][c] - s1t[tx][c]));
            }
            float dx = __fadd_rn(b2x[ty], -b1x[tx]);
            float dy = __fadd_rn(b2y[ty], -b1y[tx]);
            float cd = __fsqrt_rn(__fadd_rn(__fmul_rn(dx, dx), __fmul_rn(dy, dy)));
            g_cost[(b * MM + i) * NPAD + j] =
                __fadd_rn(__fmul_rn(0.5f, cd), __fmul_rn(0.5f, mx));
        } else {
            g_cost[(b * MM + i) * NPAD + j] = 1e30f;  // padding
        }
    }
}

// ---------------------------------------------------------------------------
// 3) exact LSA (shortest augmenting path, scipy rectangular_lsap semantics)
//    one warp per batch; fp32 margin-pruned sweep with fp64 exact updates;
//    packed-key REDUX gives approximate argmin early -> prefetch next row.
// ---------------------------------------------------------------------------
__global__ __launch_bounds__(32) void lsa_kernel() {
    const int b = blockIdx.x;
    const int lane = threadIdx.x;
    const double DINF = __longlong_as_double(0x7ff0000000000000LL);
    const float  FINF = __int_as_float(0x7f800000);

    __shared__ double u64s[MM];
    __shared__ double v64s[NPAD];
    __shared__ double s64s[NPAD];
    __shared__ float u32s[MM];
    __shared__ __align__(16) float v32s[NPAD];
    __shared__ __align__(16) float s32s[NPAD];
    __shared__ int paths[NPAD];
    __shared__ int col4rows[MM];
    __shared__ int row4cols[NPAD];
    __shared__ int SRs[MM];

    for (int t = lane; t < NPAD; t += 32) {
        v64s[t] = 0.0; v32s[t] = 0.0f; row4cols[t] = -1;
        if (t < MM) { u64s[t] = 0.0; u32s[t] = 0.0f; col4rows[t] = -1; }
    }
    const int base = lane * 16;
    unsigned validMask;
    {
        int nvalid = NN - base;
        if (nvalid < 0) nvalid = 0;
        if (nvalid > 16) nvalid = 16;
        validMask = (nvalid == 16) ? 0xffffu : ((1u << nvalid) - 1u);
    }
    __syncwarp();

    const float* costB = g_cost + (size_t)b * MM * NPAD;

    for (int cur = 0; cur < MM; cur++) {
        #pragma unroll
        for (int kk = 0; kk < 16; kk++) {
            s64s[base + kk] = DINF;
            s32s[base + kk] = FINF;
        }
        unsigned rem = validMask;
        unsigned scanned = 0;
        double minv = 0.0;
        float minv32 = 0.0f;
        int i = cur;
        int nSR = 0;
        int sink = -1;
        __syncwarp();

        while (true) {
            if (lane == 0) SRs[nSR] = i;
            nSR++;
            float dd32 = minv32 - u32s[i];
            const float* crow = costB + (size_t)i * NPAD + base;

            float4 c4[4];
            c4[0] = __ldg((const float4*)(crow + 0));
            c4[1] = __ldg((const float4*)(crow + 4));
            c4[2] = __ldg((const float4*)(crow + 8));
            c4[3] = __ldg((const float4*)(crow + 12));

            // fp32 sweep over owned columns; build candidate mask + packed key
            float se[16];
            unsigned candMask = 0;
            unsigned bestKey = 0xffffffffu;
            #pragma unroll
            for (int q = 0; q < 4; q++) {
                float4 vv = *(const float4*)(v32s + base + q * 4);
                float4 sv = *(const float4*)(s32s + base + q * 4);
                float cA[4] = {c4[q].x, c4[q].y, c4[q].z, c4[q].w};
                float vA[4] = {vv.x, vv.y, vv.z, vv.w};
                float sA[4] = {sv.x, sv.y, sv.z, sv.w};
                #pragma unroll
                for (int e = 0; e < 4; e++) {
                    int kk = q * 4 + e;
                    float r = (cA[e] - vA[e]) + dd32;
                    bool remb = (rem >> kk) & 1u;
                    bool cand = remb && (r < sA[e] + MARGIN);
                    if (cand) candMask |= (1u << kk);
                    float s_eff = cand ? fminf(sA[e], r) : sA[e];
                    se[kk] = s_eff;
                    unsigned ub = __float_as_uint(s_eff);
                    unsigned tkey = ub ^ (((unsigned)((int)ub >> 31)) | 0x80000000u);
                    unsigned key = (tkey & 0xfffffe00u) | (unsigned)(base + kk);
                    bestKey = min(bestKey, key);
                }
            }
            // exact fp64 updates for candidates only
            if (candMask) {
                double dd = minv - u64s[i];
                do {
                    int kk = __ffs(candMask) - 1;
                    candMask &= candMask - 1;
                    int j = base + kk;
                    double c64 = (double)__ldg(crow + kk);
                    double r = (c64 - v64s[j]) + dd;
                    if (r < s64s[j]) {
                        s64s[j] = r;
                        float rf = (float)r;
                        s32s[j] = rf;
                        paths[j] = i;
                        unsigned ub = __float_as_uint(rf);
                        unsigned tkey = ub ^ (((unsigned)((int)ub >> 31)) | 0x80000000u);
                        unsigned key = (tkey & 0xfffffe00u) | (unsigned)j;
                        bestKey = min(bestKey, key);
                    }
                } while (candMask);
            }
            // one REDUX: approximate min value + approximate argmin column
            unsigned mk = __reduce_min_sync(FULLMASK, bestKey);
            int jm_a = (int)(mk & 0x1ffu);
            unsigned tval = mk & 0xfffffe00u;
            float m32 = (tval & 0x80000000u) ? __uint_as_float(tval & 0x7fffffffu)
                                             : __uint_as_float(~tval);
            // speculative prefetch of the likely next row (own segment)
            int i_next = row4cols[jm_a];
            if (i_next >= 0) {
                const float* pf = costB + (size_t)i_next * NPAD + base;
                asm volatile("prefetch.global.L1 [%0];" :: "l"(pf));
            }
            // exact resolution among columns within threshold
            float thr = fmaf(6.2e-5f, fabsf(m32), m32 + MARGIN);
            unsigned resMask = 0;
            #pragma unroll
            for (int kk = 0; kk < 16; kk++) {
                if (se[kk] <= thr) resMask |= (1u << kk);
            }
            resMask &= rem;
            double bestV = DINF;
            int bestJ = 0x7fffffff;
            while (resMask) {
                int kk = __ffs(resMask) - 1;
                resMask &= resMask - 1;
                int j = base + kk;
                double sv = s64s[j];
                if (sv < bestV) { bestV = sv; bestJ = j; }  // ascending j
            }
            unsigned bal = __ballot_sync(FULLMASK, bestJ != 0x7fffffff);
            int jm;
            if (__popc(bal) == 1) {
                int src = __ffs(bal) - 1;
                minv = __shfl_sync(FULLMASK, bestV, src);
                jm   = __shfl_sync(FULLMASK, bestJ, src);
            } else {
                #pragma unroll
                for (int off = 16; off > 0; off >>= 1) {
                    double ov = __shfl_down_sync(FULLMASK, bestV, off);
                    int    oj = __shfl_down_sync(FULLMASK, bestJ, off);
                    if (ov < bestV || (ov == bestV && oj < bestJ)) { bestV = ov; bestJ = oj; }
                }
                minv = __shfl_sync(FULLMASK, bestV, 0);
                jm   = __shfl_sync(FULLMASK, bestJ, 0);
            }
            minv32 = (float)minv;
            // remove column jm
            if (lane == (jm >> 4)) {
                rem &= ~(1u << (jm & 15));
                scanned |= (1u << (jm & 15));
                s32s[jm] = FINF;
            }
            int r4c = row4cols[jm];   // shared broadcast
            if (r4c < 0) { sink = jm; break; }
            i = r4c;
        }
        __syncwarp();

        // dual updates (exact fp64, scipy order)
        for (int s = lane; s < nSR; s += 32) {
            int row = SRs[s];
            double nu = u64s[row] +
                        ((s == 0) ? minv : (minv - s64s[col4rows[row]]));
            u64s[row] = nu;
            u32s[row] = (float)nu;
        }
        {
            unsigned sm2 = scanned;
            while (sm2) {
                int kk = __ffs(sm2) - 1;
                sm2 &= sm2 - 1;
                int j = base + kk;
                double nv = v64s[j] - (minv - s64s[j]);
                v64s[j] = nv;
                v32s[j] = (float)nv;
            }
        }
        __syncwarp();
        if (lane == 0) {
            int j = sink;
            while (true) {
                int ii = paths[j];
                row4cols[j] = ii;
                int t = col4rows[ii];
                col4rows[ii] = j;
                j = t;
                if (ii == cur) break;
            }
        }
        __syncwarp();
    }

    for (int t = lane; t < MM; t += 32) g_map[b * MM + t] = col4rows[t];
}

// ---------------------------------------------------------------------------
// 4) extrapolation + output write
// ---------------------------------------------------------------------------
__global__ void extrap_kernel(const float* __restrict__ p1_boxes,
                              const float* __restrict__ p1_logits,
                              const float* __restrict__ p2_boxes,
                              const float* __restrict__ p2_logits,
                              const float* __restrict__ toff,
                              float* __restrict__ out) {
    int idx = blockIdx.x * blockDim.x + threadIdx.x;
    const int boxTotal = BB * MM * 4;
    const int logTotal = BB * MM * CC;
    if (idx < boxTotal) {
        int d = idx & 3;
        int bi = idx >> 2;
        int b = bi / MM;
        float first  = toff[b * 3 + 1] - toff[b * 3 + 0];
        float second = toff[b * 3 + 2] - toff[b * 3 + 1];
        float factor = second / first;
        int mcol = g_map[bi];
        float b2 = p2_boxes[idx];
        float c1 = p1_boxes[(b * NN + mcol) * 4 + d];
        float val = b2 + (b2 - c1) * factor;
        if (d >= 2) val = fmaxf(val, 0.0f);
        out[idx] = val;
    } else if (idx < boxTotal + logTotal) {
        int t = idx - boxTotal;
        int c = t % CC;
        int bi = t / CC;
        int b = bi / MM;
        int mcol = g_map[bi];
        float l2 = p2_logits[t];
        float l1 = p1_logits[(b * NN + mcol) * CC + c];
        out[idx] = 0.5f * (l2 + l1);
    }
}

// ---------------------------------------------------------------------------
extern "C" void kernel_launch(void* const* d_in, const int* in_sizes, int n_in,
                              void* d_out, int out_size) {
    const float* p1_boxes  = (const float*)d_in[0];
    const float* p1_logits = (const float*)d_in[1];
    const float* p2_boxes  = (const float*)d_in[2];
    const float* p2_logits = (const float*)d_in[3];
    const float* toff      = (const float*)d_in[4];
    float* out = (float*)d_out;

    {
        int total = BB * NN * CC + BB * MM * CC;
        int threads = 256;
        int blocks = (total + threads - 1) / threads;
        sigmoid_kernel<<<blocks, threads>>>(p1_logits, p2_logits);
    }
    {
        dim3 grid(NPAD / 32, (MM + 31) / 32, BB);
        dim3 block(32, 32);
        cost_kernel<<<grid, block>>>(p1_boxes, p2_boxes);
    }
    lsa_kernel<<<BB, 32>>>();
    {
        int total = BB * MM * 4 + BB * MM * CC;
        int threads = 256;
        int blocks = (total + threads - 1) / threads;
        extrap_kernel<<<blocks, threads>>>(p1_boxes, p1_logits, p2_boxes,
                                           p2_logits, toff, out);
    }
}